// round 1
// baseline (speedup 1.0000x reference)
#include <cuda_runtime.h>

// BiLingual dual EmbeddingBag(sum)
//   inputs_pri: int32 [4096, 200]
//   inputs_sec: int32 [4096, 200]
//   emb_pri:    f32   [100000, 64]
//   emb_sec:    f32   [100000, 64]
//   out:        f32   [2, 4096, 64]  (out_pri then out_sec)
//
// One warp per output row. Lane l accumulates dims {2l, 2l+1} as float2.
// Indices loaded 32-at-a-time by lanes, broadcast via shfl.

#define EB_B 4096
#define EB_S 200
#define EB_D 64
#define WARPS_PER_BLOCK 8

__global__ __launch_bounds__(WARPS_PER_BLOCK * 32)
void embed_sum_kernel(const int* __restrict__ idx_pri,
                      const int* __restrict__ idx_sec,
                      const float* __restrict__ emb_pri,
                      const float* __restrict__ emb_sec,
                      float* __restrict__ out) {
    const int warp = (blockIdx.x * blockDim.x + threadIdx.x) >> 5;
    const int lane = threadIdx.x & 31;
    if (warp >= 2 * EB_B) return;

    const int*   idx;
    const float2* tab;
    if (warp < EB_B) {
        idx = idx_pri + warp * EB_S;
        tab = reinterpret_cast<const float2*>(emb_pri);
    } else {
        idx = idx_sec + (warp - EB_B) * EB_S;
        tab = reinterpret_cast<const float2*>(emb_sec);
    }

    float accx = 0.f, accy = 0.f;

    // 6 full chunks of 32 indices (192), then an 8-index tail.
    int s = 0;
    #pragma unroll 1
    for (; s + 32 <= EB_S; s += 32) {
        const int myid = __ldg(&idx[s + lane]);
        #pragma unroll
        for (int j = 0; j < 32; ++j) {
            const int id = __shfl_sync(0xffffffffu, myid, j);
            const float2 v = __ldg(&tab[id * 32 + lane]);
            accx += v.x;
            accy += v.y;
        }
    }
    {
        const int rem = EB_S - s;  // 8
        const int myid = (lane < rem) ? __ldg(&idx[s + lane]) : 0;
        #pragma unroll
        for (int j = 0; j < 8; ++j) {
            const int id = __shfl_sync(0xffffffffu, myid, j);
            const float2 v = __ldg(&tab[id * 32 + lane]);
            accx += v.x;
            accy += v.y;
        }
    }

    float2* out2 = reinterpret_cast<float2*>(out);
    out2[warp * 32 + lane] = make_float2(accx, accy);
}

extern "C" void kernel_launch(void* const* d_in, const int* in_sizes, int n_in,
                              void* d_out, int out_size) {
    const int*   idx_pri = (const int*)d_in[0];
    const int*   idx_sec = (const int*)d_in[1];
    const float* emb_pri = (const float*)d_in[2];
    const float* emb_sec = (const float*)d_in[3];
    float* out = (float*)d_out;

    const int total_warps = 2 * EB_B;                 // 8192
    const int threads = WARPS_PER_BLOCK * 32;         // 256
    const int blocks = (total_warps + WARPS_PER_BLOCK - 1) / WARPS_PER_BLOCK;  // 1024

    embed_sum_kernel<<<blocks, threads>>>(idx_pri, idx_sec, emb_pri, emb_sec, out);
}

// round 3
// speedup vs baseline: 1.0651x; 1.0651x over previous
#include <cuda_runtime.h>

// BiLingual dual EmbeddingBag(sum)
//   inputs_pri: int32 [4096, 200]
//   inputs_sec: int32 [4096, 200]
//   emb_pri:    f32   [100000, 64]
//   emb_sec:    f32   [100000, 64]
//   out:        f32   [2, 4096, 64]  (out_pri then out_sec)
//
// One warp per output row; each half-warp (16 lanes) gathers one token row
// as float4 (16 * 16B = 256B = full row), so each LDG.128 covers 2 tokens.
// Indices staged in shared memory (coalesced), broadcast via LDS.

#define EB_B 4096
#define EB_S 200
#define EB_D 64
#define WPB 8            // warps per block
#define NBLK_PER_TAB (EB_B / WPB)   // 512

__global__ __launch_bounds__(WPB * 32)
void embed_sum_kernel(const int* __restrict__ idx_pri,
                      const int* __restrict__ idx_sec,
                      const float* __restrict__ emb_pri,
                      const float* __restrict__ emb_sec,
                      float* __restrict__ out) {
    __shared__ int sidx[WPB * EB_S];

    const int tid  = threadIdx.x;
    const int warp = tid >> 5;
    const int lane = tid & 31;
    const int half = lane >> 4;     // which token of the pair
    const int hl   = lane & 15;     // lane within half-warp (dim quad)

    const int*    idx;
    const float4* tab;
    int           row_base;         // first output row of this block
    if (blockIdx.x < NBLK_PER_TAB) {
        idx      = idx_pri;
        tab      = reinterpret_cast<const float4*>(emb_pri);
        row_base = blockIdx.x * WPB;
    } else {
        idx      = idx_sec;
        tab      = reinterpret_cast<const float4*>(emb_sec);
        row_base = (blockIdx.x - NBLK_PER_TAB) * WPB;
    }

    // Stage this block's 8x200 indices (coalesced).
    {
        const int* gsrc = idx + row_base * EB_S;
        #pragma unroll
        for (int i = tid; i < WPB * EB_S; i += WPB * 32)
            sidx[i] = gsrc[i];
    }
    __syncthreads();

    const int* my = &sidx[warp * EB_S];

    float4 acc = make_float4(0.f, 0.f, 0.f, 0.f);

    // 100 iterations, 2 tokens each. Unroll 4 -> 4 LDG.128 in flight.
    #pragma unroll 4
    for (int j = 0; j < EB_S; j += 2) {
        const int id = my[j + half];
        const float4 v = __ldg(&tab[id * (EB_D / 4) + hl]);
        acc.x += v.x;
        acc.y += v.y;
        acc.z += v.z;
        acc.w += v.w;
    }

    // Combine the two half-warp partials.
    acc.x += __shfl_xor_sync(0xffffffffu, acc.x, 16);
    acc.y += __shfl_xor_sync(0xffffffffu, acc.y, 16);
    acc.z += __shfl_xor_sync(0xffffffffu, acc.z, 16);
    acc.w += __shfl_xor_sync(0xffffffffu, acc.w, 16);

    if (half == 0) {
        const int out_row = (blockIdx.x < NBLK_PER_TAB ? 0 : EB_B) + row_base + warp;
        float4* out4 = reinterpret_cast<float4*>(out);
        out4[out_row * (EB_D / 4) + hl] = acc;
    }
}

extern "C" void kernel_launch(void* const* d_in, const int* in_sizes, int n_in,
                              void* d_out, int out_size) {
    const int*   idx_pri = (const int*)d_in[0];
    const int*   idx_sec = (const int*)d_in[1];
    const float* emb_pri = (const float*)d_in[2];
    const float* emb_sec = (const float*)d_in[3];
    float* outp = (float*)d_out;

    const int blocks  = 2 * NBLK_PER_TAB;   // 1024
    const int threads = WPB * 32;           // 256

    embed_sum_kernel<<<blocks, threads>>>(idx_pri, idx_sec, emb_pri, emb_sec, outp);
}